// round 6
// baseline (speedup 1.0000x reference)
#include <cuda_runtime.h>
#include <cuda_fp16.h>

#define NMAX   50000
#define EMAX   800000
#define H      96
#define CIN    128
#define COUT   40
#define NLAYER 5
#define DTC    0.05f

// ---------------- device scratch (static, no allocs) ----------------
__device__ int   g_deg[NMAX];
__device__ int   g_rowptr[NMAX + 1];
__device__ int   g_cursor[NMAX];
__device__ float g_deginv[NMAX];
__device__ int   g_srcs[EMAX];
// fp16 state ping-pong: interleaved (X,Y) half2 per channel (row = 96 half2 = 24 uint4)
__device__ __align__(16) __half2 g_XY0[(size_t)NMAX * H];
__device__ __align__(16) __half2 g_XY1[(size_t)NMAX * H];
// e4m3 gather mirror ping-pong: (X,Y) fp8 pairs, row = 192 B = 24 uint2
__device__ __align__(16) uint2 g_F80[(size_t)NMAX * 24];
__device__ __align__(16) uint2 g_F81[(size_t)NMAX * 24];

// ---------------- f32x2 packed-FMA helpers ----------------
__device__ __forceinline__ unsigned long long pack2(float v) {
    unsigned long long r; unsigned int u = __float_as_uint(v);
    asm("mov.b64 %0, {%1, %1};" : "=l"(r) : "r"(u));
    return r;
}
__device__ __forceinline__ unsigned long long packxy(float lo, float hi) {
    unsigned long long r;
    asm("mov.b64 %0, {%1, %2};" : "=l"(r) : "f"(lo), "f"(hi));
    return r;
}
__device__ __forceinline__ void unpack2(unsigned long long v, float& a, float& b) {
    unsigned int x, y;
    asm("mov.b64 {%0, %1}, %2;" : "=r"(x), "=r"(y) : "l"(v));
    a = __uint_as_float(x); b = __uint_as_float(y);
}
__device__ __forceinline__ void ffma2(unsigned long long& d,
                                      unsigned long long a, unsigned long long b) {
    asm("fma.rn.f32x2 %0, %1, %2, %0;" : "+l"(d) : "l"(a), "l"(b));
}

// ---------------- fp8 (e4m3) helpers ----------------
__device__ __forceinline__ unsigned short f32_to_e4m3x2(float lo, float hi) {
    unsigned short r;
    asm("cvt.rn.satfinite.e4m3x2.f32 %0, %1, %2;" : "=h"(r) : "f"(hi), "f"(lo));
    return r;
}
__device__ __forceinline__ __half2 e4m3x2_to_h2(unsigned int v16) {
    unsigned int r;
    unsigned short s = (unsigned short)v16;
    asm("cvt.rn.f16x2.e4m3x2 %0, %1;" : "=r"(r) : "h"(s));
    return *(__half2*)&r;
}

// ---------------- CSR build ----------------
__global__ void k_deg(const int* __restrict__ dst, int E) {
    int e = blockIdx.x * blockDim.x + threadIdx.x;
    if (e < E) atomicAdd(&g_deg[dst[e]], 1);
}

__global__ void k_scan(int N) {
    __shared__ int sm[1024];
    int tid = threadIdx.x;
    int per = (N + 1023) >> 10;
    int b = tid * per;
    int e = b + per; if (e > N) e = N; if (b > N) b = N;
    int sum = 0;
    for (int i = b; i < e; ++i) sum += g_deg[i];
    sm[tid] = sum;
    __syncthreads();
    for (int off = 1; off < 1024; off <<= 1) {
        int v = 0;
        if (tid >= off) v = sm[tid - off];
        __syncthreads();
        sm[tid] += v;
        __syncthreads();
    }
    int run = sm[tid] - sum;  // exclusive prefix
    for (int i = b; i < e; ++i) {
        int dg = g_deg[i];
        g_rowptr[i] = run;
        g_cursor[i] = run;
        g_deginv[i] = 1.0f / (float)(dg > 1 ? dg : 1);
        run += dg;
    }
    if (tid == 0) g_rowptr[N] = sm[1023];
}

__global__ void k_scatter(const int* __restrict__ src, const int* __restrict__ dst, int E) {
    int e = blockIdx.x * blockDim.x + threadIdx.x;
    if (e < E) {
        int p = atomicAdd(&g_cursor[dst[e]], 1);
        g_srcs[p] = src[e];
    }
}

// ---------------- lift ----------------
// Pair-GEMM: tanh(x @ [Wx,Wy]) via f32x2, packed lane pair IS (X_c, Y_c).
// 256 threads, block tile 256 rows x 32 pairs, thread tile 8 rows x 4 pairs.
// Writes fp16 state + e4m3 gather mirror.
__global__ __launch_bounds__(256) void k_lift(
        const float* __restrict__ x,
        const float* __restrict__ Wx, const float* __restrict__ bx,
        const float* __restrict__ Wy, const float* __restrict__ by,
        int N) {
    __shared__ __align__(16) float  xs[256][33];
    __shared__ __align__(16) float2 ws[32][32];   // (Wx,Wy) pairs
    int tid = threadIdx.x;
    int tx = tid & 7;        // pair group (8), 4 pairs each
    int ty = tid >> 3;       // row group (32), 8 rows each
    int cb = blockIdx.y;     // 0..2 (32 pairs each)
    int row0 = blockIdx.x * 256;

    unsigned long long acc[8][4];
#pragma unroll
    for (int i = 0; i < 8; ++i)
#pragma unroll
        for (int p = 0; p < 4; ++p) acc[i][p] = 0ull;

    for (int kt = 0; kt < CIN; kt += 32) {
        // xs: 256 rows x 32 k = 2048 float4 -> 8 per thread
#pragma unroll
        for (int j = 0; j < 8; ++j) {
            int f4 = tid + j * 256;
            int r = f4 >> 3;
            int kq = f4 & 7;
            float4 v = make_float4(0.f, 0.f, 0.f, 0.f);
            int gr = row0 + r;
            if (gr < N) v = *(const float4*)(x + (size_t)gr * CIN + kt + kq * 4);
            xs[r][kq * 4 + 0] = v.x; xs[r][kq * 4 + 1] = v.y;
            xs[r][kq * 4 + 2] = v.z; xs[r][kq * 4 + 3] = v.w;
        }
        // ws: 32 k x 32 pairs -> 4 per thread
#pragma unroll
        for (int j = 0; j < 4; ++j) {
            int idx = tid + j * 256;   // 0..1023
            int k = idx >> 5;
            int p = idx & 31;
            int gp = cb * 32 + p;
            int gk = kt + k;
            ws[k][p] = make_float2(Wx[gk * H + gp], Wy[gk * H + gp]);
        }
        __syncthreads();
#pragma unroll
        for (int k = 0; k < 32; ++k) {
            const unsigned long long* wp =
                reinterpret_cast<const unsigned long long*>(&ws[k][tx * 4]);
            unsigned long long b0 = wp[0], b1 = wp[1], b2 = wp[2], b3 = wp[3];
#pragma unroll
            for (int i = 0; i < 8; ++i) {
                unsigned long long a2 = pack2(xs[ty * 8 + i][k]);
                ffma2(acc[i][0], a2, b0);
                ffma2(acc[i][1], a2, b1);
                ffma2(acc[i][2], a2, b2);
                ffma2(acc[i][3], a2, b3);
            }
        }
        __syncthreads();
    }
    int c0 = cb * 32 + tx * 4;   // channel base (4 channels per thread)
    float bxv[4], byv[4];
#pragma unroll
    for (int p = 0; p < 4; ++p) { bxv[p] = bx[c0 + p]; byv[p] = by[c0 + p]; }
    uint2* f8base = g_F80;
#pragma unroll
    for (int i = 0; i < 8; ++i) {
        int gr = row0 + ty * 8 + i;
        if (gr < N) {
            float Xc[4], Yc[4];
#pragma unroll
            for (int p = 0; p < 4; ++p) {
                float xr, yr;
                unpack2(acc[i][p], xr, yr);
                Xc[p] = tanhf(xr + bxv[p]);
                Yc[p] = tanhf(yr + byv[p]);
            }
            uint4 hv;
            __half2 h0 = __floats2half2_rn(Xc[0], Yc[0]);
            __half2 h1 = __floats2half2_rn(Xc[1], Yc[1]);
            __half2 h2 = __floats2half2_rn(Xc[2], Yc[2]);
            __half2 h3 = __floats2half2_rn(Xc[3], Yc[3]);
            hv.x = *(unsigned int*)&h0; hv.y = *(unsigned int*)&h1;
            hv.z = *(unsigned int*)&h2; hv.w = *(unsigned int*)&h3;
            *(uint4*)(&g_XY0[(size_t)gr * H + c0]) = hv;
            uint2 f8;
            f8.x = (unsigned int)f32_to_e4m3x2(Xc[0], Yc[0])
                 | ((unsigned int)f32_to_e4m3x2(Xc[1], Yc[1]) << 16);
            f8.y = (unsigned int)f32_to_e4m3x2(Xc[2], Yc[2])
                 | ((unsigned int)f32_to_e4m3x2(Xc[3], Yc[3]) << 16);
            f8base[(size_t)gr * 24 + (c0 >> 2)] = f8;
        }
    }
}

// ---------------- one LVConv layer ----------------
// warp per dst node. Gather: lanes 0..23 load 8 e4m3 (uint2 = 4 channel-pairs)
// per edge, cvt->half2, HADD2 accumulate. Epilogue: fp32 Euler update from the
// fp16 state row, write fp16 state + fp8 mirror.
__global__ __launch_bounds__(256) void k_layer(
        const uint4* __restrict__ XYin,     // fp16 rows of 24 uint4
        const uint2* __restrict__ F8in,     // fp8 rows of 24 uint2
        uint4* __restrict__ XYout,
        uint2* __restrict__ F8out,
        const float* __restrict__ al, const float* __restrict__ be,
        const float* __restrict__ ga, const float* __restrict__ de,
        int N) {
    int w = (blockIdx.x * blockDim.x + threadIdx.x) >> 5;
    int lane = threadIdx.x & 31;
    if (w >= N) return;
    bool act = lane < 24;
    int s0 = __ldg(&g_rowptr[w]);
    int s1 = __ldg(&g_rowptr[w + 1]);

    __half2 acc0 = __floats2half2_rn(0.f, 0.f);
    __half2 acc1 = acc0, acc2 = acc0, acc3 = acc0;

    int e = s0;
    for (; e + 4 <= s1; e += 4) {
        int sA = __ldg(&g_srcs[e + 0]);
        int sB = __ldg(&g_srcs[e + 1]);
        int sC = __ldg(&g_srcs[e + 2]);
        int sD = __ldg(&g_srcs[e + 3]);
        if (act) {
            uint2 vA = __ldg(F8in + (size_t)sA * 24 + lane);
            uint2 vB = __ldg(F8in + (size_t)sB * 24 + lane);
            uint2 vC = __ldg(F8in + (size_t)sC * 24 + lane);
            uint2 vD = __ldg(F8in + (size_t)sD * 24 + lane);
            acc0 = __hadd2(acc0, __hadd2(__hadd2(e4m3x2_to_h2(vA.x), e4m3x2_to_h2(vB.x)),
                                         __hadd2(e4m3x2_to_h2(vC.x), e4m3x2_to_h2(vD.x))));
            acc1 = __hadd2(acc1, __hadd2(__hadd2(e4m3x2_to_h2(vA.x >> 16), e4m3x2_to_h2(vB.x >> 16)),
                                         __hadd2(e4m3x2_to_h2(vC.x >> 16), e4m3x2_to_h2(vD.x >> 16))));
            acc2 = __hadd2(acc2, __hadd2(__hadd2(e4m3x2_to_h2(vA.y), e4m3x2_to_h2(vB.y)),
                                         __hadd2(e4m3x2_to_h2(vC.y), e4m3x2_to_h2(vD.y))));
            acc3 = __hadd2(acc3, __hadd2(__hadd2(e4m3x2_to_h2(vA.y >> 16), e4m3x2_to_h2(vB.y >> 16)),
                                         __hadd2(e4m3x2_to_h2(vC.y >> 16), e4m3x2_to_h2(vD.y >> 16))));
        }
    }
    for (; e < s1; ++e) {
        int s = __ldg(&g_srcs[e]);
        if (act) {
            uint2 v = __ldg(F8in + (size_t)s * 24 + lane);
            acc0 = __hadd2(acc0, e4m3x2_to_h2(v.x));
            acc1 = __hadd2(acc1, e4m3x2_to_h2(v.x >> 16));
            acc2 = __hadd2(acc2, e4m3x2_to_h2(v.y));
            acc3 = __hadd2(acc3, e4m3x2_to_h2(v.y >> 16));
        }
    }
    if (!act) return;

    float dinv = __ldg(&g_deginv[w]);
    float2 a0 = __half22float2(acc0);
    float2 a1 = __half22float2(acc1);
    float2 a2 = __half22float2(acc2);
    float2 a3 = __half22float2(acc3);
    float aggX[4] = {a0.x * dinv, a1.x * dinv, a2.x * dinv, a3.x * dinv};
    float aggY[4] = {a0.y * dinv, a1.y * dinv, a2.y * dinv, a3.y * dinv};

    int c0 = lane * 4;
    size_t rbase = (size_t)w * 24 + lane;
    uint4 sv = __ldg(XYin + rbase);
    float2 s0f = __half22float2(*(__half2*)&sv.x);
    float2 s1f = __half22float2(*(__half2*)&sv.y);
    float2 s2f = __half22float2(*(__half2*)&sv.z);
    float2 s3f = __half22float2(*(__half2*)&sv.w);

    float4 alv = *(const float4*)(al + c0);
    float4 bev = *(const float4*)(be + c0);
    float4 gav = *(const float4*)(ga + c0);
    float4 dev = *(const float4*)(de + c0);

    float Xn0 = s0f.x + DTC * s0f.x * (alv.x - bev.x * aggY[0]);
    float Yn0 = s0f.y + DTC * s0f.y * (-gav.x + dev.x * aggX[0]);
    float Xn1 = s1f.x + DTC * s1f.x * (alv.y - bev.y * aggY[1]);
    float Yn1 = s1f.y + DTC * s1f.y * (-gav.y + dev.y * aggX[1]);
    float Xn2 = s2f.x + DTC * s2f.x * (alv.z - bev.z * aggY[2]);
    float Yn2 = s2f.y + DTC * s2f.y * (-gav.z + dev.z * aggX[2]);
    float Xn3 = s3f.x + DTC * s3f.x * (alv.w - bev.w * aggY[3]);
    float Yn3 = s3f.y + DTC * s3f.y * (-gav.w + dev.w * aggX[3]);

    __half2 h0 = __floats2half2_rn(Xn0, Yn0);
    __half2 h1 = __floats2half2_rn(Xn1, Yn1);
    __half2 h2 = __floats2half2_rn(Xn2, Yn2);
    __half2 h3 = __floats2half2_rn(Xn3, Yn3);
    uint4 hv;
    hv.x = *(unsigned int*)&h0; hv.y = *(unsigned int*)&h1;
    hv.z = *(unsigned int*)&h2; hv.w = *(unsigned int*)&h3;
    XYout[rbase] = hv;

    uint2 f8;
    f8.x = (unsigned int)f32_to_e4m3x2(Xn0, Yn0)
         | ((unsigned int)f32_to_e4m3x2(Xn1, Yn1) << 16);
    f8.y = (unsigned int)f32_to_e4m3x2(Xn2, Yn2)
         | ((unsigned int)f32_to_e4m3x2(Xn3, Yn3) << 16);
    F8out[rbase] = f8;
}

// ---------------- readout: out = [X|Y] @ Wr + br, fp16 state, f32x2 math ----
__global__ __launch_bounds__(128) void k_readout(
        const uint4* __restrict__ XY,       // rows of 24 uint4
        const float* __restrict__ Wr, const float* __restrict__ br,
        float* __restrict__ out, int N) {
    __shared__ float2 xs2[128][33];
    __shared__ float  wsX[32][COUT];
    __shared__ float  wsY[32][COUT];
    int tid = threadIdx.x;
    int tx = tid & 7;
    int ty = tid >> 3;
    int row0 = blockIdx.x * 128;
    // acc2[p][j]: packed rows (2p, 2p+1), col j
    unsigned long long acc2[4][5];
#pragma unroll
    for (int p = 0; p < 4; ++p)
#pragma unroll
        for (int j = 0; j < 5; ++j) acc2[p][j] = 0ull;

    for (int kt = 0; kt < H; kt += 32) {
#pragma unroll
        for (int j = 0; j < 8; ++j) {
            int u4 = tid + j * 128;
            int r = u4 >> 3;
            int q = u4 & 7;
            int gr = row0 + r;
            uint4 v = make_uint4(0u, 0u, 0u, 0u);
            if (gr < N) v = __ldg(XY + (size_t)gr * 24 + (kt >> 2) + q);
            int cc = q * 4;
            xs2[r][cc + 0] = __half22float2(*(__half2*)&v.x);
            xs2[r][cc + 1] = __half22float2(*(__half2*)&v.y);
            xs2[r][cc + 2] = __half22float2(*(__half2*)&v.z);
            xs2[r][cc + 3] = __half22float2(*(__half2*)&v.w);
        }
#pragma unroll
        for (int j = 0; j < 10; ++j) {
            int idx = tid + j * 128;
            if (idx < 32 * COUT) {
                int k = idx / COUT;
                int c = idx - k * COUT;
                wsX[k][c] = Wr[(size_t)(kt + k) * COUT + c];
                wsY[k][c] = Wr[(size_t)(H + kt + k) * COUT + c];
            }
        }
        __syncthreads();
#pragma unroll
        for (int k = 0; k < 32; ++k) {
            float2 xv[8];
#pragma unroll
            for (int i = 0; i < 8; ++i) xv[i] = xs2[ty * 8 + i][k];
            unsigned long long XA[4], YA[4];
#pragma unroll
            for (int p = 0; p < 4; ++p) {
                XA[p] = packxy(xv[2 * p].x, xv[2 * p + 1].x);
                YA[p] = packxy(xv[2 * p].y, xv[2 * p + 1].y);
            }
#pragma unroll
            for (int j = 0; j < 5; ++j) {
                unsigned long long wxj = pack2(wsX[k][tx * 5 + j]);
                unsigned long long wyj = pack2(wsY[k][tx * 5 + j]);
#pragma unroll
                for (int p = 0; p < 4; ++p) {
                    ffma2(acc2[p][j], XA[p], wxj);
                    ffma2(acc2[p][j], YA[p], wyj);
                }
            }
        }
        __syncthreads();
    }
#pragma unroll
    for (int p = 0; p < 4; ++p) {
        int gr0 = row0 + ty * 8 + 2 * p;
#pragma unroll
        for (int j = 0; j < 5; ++j) {
            float vlo, vhi;
            unpack2(acc2[p][j], vlo, vhi);
            float bb = br[tx * 5 + j];
            if (gr0 < N)     out[(size_t)gr0 * COUT + tx * 5 + j] = vlo + bb;
            if (gr0 + 1 < N) out[(size_t)(gr0 + 1) * COUT + tx * 5 + j] = vhi + bb;
        }
    }
}

// ---------------- launch ----------------
extern "C" void kernel_launch(void* const* d_in, const int* in_sizes, int n_in,
                              void* d_out, int out_size) {
    const float* x  = (const float*)d_in[0];
    const int*   ei = (const int*)d_in[1];
    const float* Wx = (const float*)d_in[2];
    const float* bx = (const float*)d_in[3];
    const float* Wy = (const float*)d_in[4];
    const float* by = (const float*)d_in[5];
    const float* al = (const float*)d_in[6];
    const float* be = (const float*)d_in[7];
    const float* ga = (const float*)d_in[8];
    const float* de = (const float*)d_in[9];
    const float* Wr = (const float*)d_in[10];
    const float* br = (const float*)d_in[11];
    float* out = (float*)d_out;

    int N = in_sizes[0] / CIN;
    int E = in_sizes[1] / 2;
    if (N > NMAX) N = NMAX;
    if (E > EMAX) E = EMAX;
    const int* srcp = ei;
    const int* dstp = ei + E;

    void* degp;
    cudaGetSymbolAddress(&degp, g_deg);
    cudaMemsetAsync(degp, 0, (size_t)N * sizeof(int));

    k_deg<<<(E + 255) / 256, 256>>>(dstp, E);
    k_scan<<<1, 1024>>>(N);
    k_scatter<<<(E + 255) / 256, 256>>>(srcp, dstp, E);

    dim3 gl((N + 255) / 256, 3);
    k_lift<<<gl, 256>>>(x, Wx, bx, Wy, by, N);

    uint4* XYb[2]; uint2* F8b[2];
    cudaGetSymbolAddress((void**)&XYb[0], g_XY0);
    cudaGetSymbolAddress((void**)&XYb[1], g_XY1);
    cudaGetSymbolAddress((void**)&F8b[0], g_F80);
    cudaGetSymbolAddress((void**)&F8b[1], g_F81);

    int layerBlocks = (N * 32 + 255) / 256;
    for (int l = 0; l < NLAYER; ++l) {
        k_layer<<<layerBlocks, 256>>>(XYb[l & 1], F8b[l & 1],
                                      XYb[(l + 1) & 1], F8b[(l + 1) & 1],
                                      al + l * H, be + l * H, ga + l * H, de + l * H, N);
    }
    k_readout<<<(N + 127) / 128, 128>>>(XYb[NLAYER & 1], Wr, br, out, N);
}